// round 4
// baseline (speedup 1.0000x reference)
#include <cuda_runtime.h>
#include <math.h>

// ---------------- problem constants ----------------
#define NNODES 325
#define BATCH  64
#define TSTEPS 12
#define HORIZON 12
#define UNITS  64
#define DIN    2
#define NB (NNODES*BATCH)        // 20800 rows
#define F3MAX 384
#define PADW 352
#define GRID 148                 // <= SM count -> all CTAs resident -> spin barrier safe
#define NTH  512
#define NWARPS 16
#define GWARPS (GRID*NWARPS)

typedef unsigned long long ull;

// ---------------- device scratch (no allocs allowed) ----------------
__device__ float g_h0[NB*UNITS];
__device__ float g_h1[NB*UNITS];
__device__ float g_din[NB];
__device__ float g_xk[NB*F3MAX];      // row stride = F3 of current cell
__device__ float g_ru[NB*2*UNITS];    // u gate stored at cols [64,128)
__device__ int   g_cnt1[NNODES];
__device__ int   g_cnt2[NNODES];
__device__ ull   g_s1[NNODES*PADW];   // packed (col, val) for S
__device__ ull   g_s2[NNODES*PADW];   // packed (col, val) for 2*S@S
__device__ unsigned g_bar;

__global__ void init_bar(){ g_bar = 0u; }

// ---------------- helpers ----------------
__device__ __forceinline__ ull packe(int c, float v){
    return ((ull)__float_as_uint(v) << 32) | (unsigned)c;
}
__device__ __forceinline__ void fma2(ull &acc, ull a, ull b){
    asm("fma.rn.f32x2 %0,%1,%2,%0;" : "+l"(acc) : "l"(a), "l"(b));
}

// grid barrier: monotonic counter; all CTAs resident by construction.
__device__ __forceinline__ void gsync(unsigned &epoch){
    __threadfence();                       // release my writes (gpu scope)
    __syncthreads();                       // all block threads fenced before arrive
    if (threadIdx.x == 0){
        epoch += GRID;
        atomicAdd(&g_bar, 1u);
        while (*(volatile unsigned*)&g_bar < epoch) { }
    }
    __syncthreads();
    __threadfence();                       // acquire: invalidate L1 before fresh reads
}

// ---------------- x0 source gather ----------------
__device__ __forceinline__ float src_val(int k, int b, int f, int Fx, int xsel, int hsel,
                                          const float* __restrict__ inp_t, int F3v, int phase){
    int rb = k*BATCH + b;
    if (phase) return g_xk[rb*F3v + Fx + f];        // rh columns
    if (f < Fx){
        if (xsel == 2) return inp_t[b*(NNODES*DIN) + k*DIN + f];
        if (xsel == 1) return g_din[rb];
        return g_h0[rb*UNITS + f];
    }
    const float* H = hsel ? g_h1 : g_h0;
    return H[rb*UNITS + (f - Fx)];
}

// ---------------- fused concat + Chebyshev diffusion (flat, warp-per-task) ----------------
// phase 0 (gate): x0=[x,h] -> g_xk[0:F); x1=S x0 -> [F,2F); x2=S2 x0 - x0 -> [2F,3F)
// phase 1 (cand): rh at [Fx,F) -> S rh at [F+Fx,2F), S2 rh - rh at [2F+Fx,3F)
__device__ void gconv_phase(int phase, int xsel, int Fx, int hsel,
                            const float* __restrict__ inp_t, int wg, int lane){
    const int F = Fx + UNITS, F3v = 3*F;
    const int ncols = phase ? UNITS : F;
    const int nch = (ncols + 31)/32;
    const int woff = phase ? Fx : 0;
    const int ntasks = nch*BATCH*NNODES;
    for (int t = wg; t < ntasks; t += GWARPS){
        int m = t % NNODES; int r = t / NNODES;
        int b = r % BATCH;  int ch = r / BATCH;
        int f  = ch*32 + lane;
        bool val = (f < ncols);
        int fc = val ? f : (ncols - 1);
        float own = src_val(m, b, fc, Fx, xsel, hsel, inp_t, F3v, phase);

        float a1a = 0.f, a1b = 0.f;
        {
            int c1 = g_cnt1[m];
            const ull* e = g_s1 + m*PADW;
            int j = 0;
            for (; j + 1 < c1; j += 2){
                ull e0 = e[j], e1v = e[j+1];
                int k0 = (int)(unsigned)e0;  float v0 = __uint_as_float((unsigned)(e0>>32));
                int k1 = (int)(unsigned)e1v; float v1 = __uint_as_float((unsigned)(e1v>>32));
                a1a += v0 * src_val(k0, b, fc, Fx, xsel, hsel, inp_t, F3v, phase);
                a1b += v1 * src_val(k1, b, fc, Fx, xsel, hsel, inp_t, F3v, phase);
            }
            if (j < c1){
                ull e0 = e[j];
                int k0 = (int)(unsigned)e0; float v0 = __uint_as_float((unsigned)(e0>>32));
                a1a += v0 * src_val(k0, b, fc, Fx, xsel, hsel, inp_t, F3v, phase);
            }
        }
        float a2a = 0.f, a2b = 0.f;
        {
            int c2 = g_cnt2[m];
            const ull* e = g_s2 + m*PADW;
            int j = 0;
            for (; j + 1 < c2; j += 2){
                ull e0 = e[j], e1v = e[j+1];
                int k0 = (int)(unsigned)e0;  float v0 = __uint_as_float((unsigned)(e0>>32));
                int k1 = (int)(unsigned)e1v; float v1 = __uint_as_float((unsigned)(e1v>>32));
                a2a += v0 * src_val(k0, b, fc, Fx, xsel, hsel, inp_t, F3v, phase);
                a2b += v1 * src_val(k1, b, fc, Fx, xsel, hsel, inp_t, F3v, phase);
            }
            if (j < c2){
                ull e0 = e[j];
                int k0 = (int)(unsigned)e0; float v0 = __uint_as_float((unsigned)(e0>>32));
                a2a += v0 * src_val(k0, b, fc, Fx, xsel, hsel, inp_t, F3v, phase);
            }
        }
        float a1 = a1a + a1b;
        float a2 = (a2a + a2b) - own;       // g_s2 already holds 2*S@S
        if (val){
            int orow = (m*BATCH + b)*F3v;
            if (!phase) g_xk[orow + f] = own;
            g_xk[orow + F   + woff + f] = a1;
            g_xk[orow + 2*F + woff + f] = a2;
        }
    }
}

// ---------------- GEMM with fused GRU epilogues (packed-K f32x2, no splat movs) ----------------
// C = g_xk(NB x F3) @ W(F3 x ONUM) + bias
// epi 0 (gate): s=sigmoid; n<64: xk[r][Fx+n]=s*H  ; n>=64: g_ru[r][n]=s
// epi 1 (cand): c=tanh; H = u*H + (1-u)*c
// epi 2: epi1 + projection out/g_din
#define BK 16
#define BSTR 20   // Bs row stride (floats); 16B-aligned

template<int ONUM>
__device__ void gemm_phase(int F3v, const float* __restrict__ W, const float* __restrict__ bias,
                           int hsel, int epi, int Fx,
                           const float* __restrict__ pW, const float* __restrict__ pb,
                           float* __restrict__ out_t,
                           float* As, float* Bs, int tid){
    const int CT = ONUM/4;          // col-threads (32 gate, 16 cand)
    const int RT = NTH/CT;          // row-threads (16 gate, 32 cand)
    const int BM = RT*4;            // 64 gate, 128 cand
    const int T  = (NB + BM - 1)/BM;
    float* H = hsel ? g_h1 : g_h0;

    const int tx = tid % CT, ty = tid / CT;
    const int ktiles = (F3v + BK - 1)/BK;

    for (int tile = blockIdx.x; tile < T; tile += GRID){
        int row0 = tile*BM;
        ull acc[4][4];
        #pragma unroll
        for (int i = 0; i < 4; i++)
            #pragma unroll
            for (int c = 0; c < 4; c++) acc[i][c] = 0ull;

        for (int kt = 0; kt < ktiles; kt++){
            int k0 = kt*BK;
            // stage A: As[m][k], k-contiguous
            #pragma unroll
            for (int l = 0; l < (BM*BK)/NTH; l++){
                int idx = l*NTH + tid;
                int k = idx & (BK-1), m = idx / BK;
                int r = row0 + m, kk = k0 + k;
                As[m*BK + k] = (r < NB && kk < F3v) ? g_xk[r*F3v + kk] : 0.f;
            }
            // stage B transposed: Bs[n][k]
            #pragma unroll
            for (int l = 0; l < (ONUM*BK)/NTH; l++){
                int idx = l*NTH + tid;
                int n = idx % ONUM, k = idx / ONUM;
                int kk = k0 + k;
                Bs[n*BSTR + k] = (kk < F3v) ? W[kk*ONUM + n] : 0.f;
            }
            __syncthreads();
            #pragma unroll
            for (int kk = 0; kk < BK; kk += 4){
                ull a[4][2], bb[4][2];
                #pragma unroll
                for (int i = 0; i < 4; i++){
                    const ull* ap = (const ull*)&As[(ty*4 + i)*BK + kk];
                    a[i][0] = ap[0]; a[i][1] = ap[1];
                }
                #pragma unroll
                for (int c = 0; c < 4; c++){
                    const ull* bp = (const ull*)&Bs[(tx*4 + c)*BSTR + kk];
                    bb[c][0] = bp[0]; bb[c][1] = bp[1];
                }
                #pragma unroll
                for (int i = 0; i < 4; i++)
                    #pragma unroll
                    for (int c = 0; c < 4; c++){
                        fma2(acc[i][c], a[i][0], bb[c][0]);
                        fma2(acc[i][c], a[i][1], bb[c][1]);
                    }
            }
            __syncthreads();
        }

        // epilogue
        #pragma unroll
        for (int i = 0; i < 4; i++){
            int r = row0 + ty*4 + i;
            bool valid = (r < NB);
            int rc = valid ? r : 0;
            float pv = 0.f;
            #pragma unroll
            for (int c = 0; c < 4; c++){
                float lo = __uint_as_float((unsigned)acc[i][c]);
                float hi = __uint_as_float((unsigned)(acc[i][c] >> 32));
                int n = tx*4 + c;
                float v = lo + hi + bias[n];
                if (epi == 0){
                    float s = 1.f/(1.f + expf(-v));
                    if (n < UNITS){
                        if (valid) g_xk[rc*F3v + Fx + n] = s * H[rc*UNITS + n];
                    } else {
                        if (valid) g_ru[rc*(2*UNITS) + n] = s;
                    }
                } else {
                    float cc = tanhf(v);
                    float u  = g_ru[rc*(2*UNITS) + UNITS + n];
                    float h  = H[rc*UNITS + n];
                    float hn = u*h + (1.f - u)*cc;
                    if (valid) H[rc*UNITS + n] = hn;
                    if (epi == 2) pv += hn * pW[n];
                }
            }
            if (epi == 2){
                // reduce across CT=16 col-threads (contiguous 16-lane groups)
                #pragma unroll
                for (int o = 8; o > 0; o >>= 1)
                    pv += __shfl_xor_sync(0xffffffffu, pv, o);
                if (tx == 0 && valid){
                    pv += pb[0];
                    int n = rc / BATCH, b = rc % BATCH;
                    out_t[b*NNODES + n] = pv;
                    g_din[rc] = pv;
                }
            }
        }
    }
}

// ---------------- one GRU cell ----------------
__device__ void run_cell(int xsel, int Fx, int hsel, const float* inp_t,
                         const float* gW, const float* gb,
                         const float* cW, const float* cb,
                         int cand_epi, const float* pW, const float* pb, float* out_t,
                         unsigned &epoch, int tid, int wg, int lane, float* As, float* Bs){
    int F3v = 3*(Fx + UNITS);
    gconv_phase(0, xsel, Fx, hsel, inp_t, wg, lane);
    gsync(epoch);
    gemm_phase<2*UNITS>(F3v, gW, gb, hsel, 0, Fx, nullptr, nullptr, nullptr, As, Bs, tid);
    gsync(epoch);
    gconv_phase(1, xsel, Fx, hsel, nullptr, wg, lane);
    gsync(epoch);
    gemm_phase<UNITS>(F3v, cW, cb, hsel, cand_epi, Fx, pW, pb, out_t, As, Bs, tid);
    gsync(epoch);
}

// ---------------- the whole network in one launch ----------------
__global__ void __launch_bounds__(NTH, 1)
dcrnn_persistent(const float* __restrict__ inputs, const float* __restrict__ S,
                 const float* e0gW, const float* e0gb, const float* e0cW, const float* e0cb,
                 const float* e1gW, const float* e1gb, const float* e1cW, const float* e1cb,
                 const float* d0gW, const float* d0gb, const float* d0cW, const float* d0cb,
                 const float* d1gW, const float* d1gb, const float* d1cW, const float* d1cb,
                 const float* pW,  const float* pb,  float* __restrict__ out)
{
    __shared__ float As[128*BK];     // 8 KB
    __shared__ float Bs[128*BSTR];   // 10 KB
    int tid = threadIdx.x;
    int lane = tid & 31, wid = tid >> 5;
    int wg = blockIdx.x*NWARPS + wid;
    unsigned epoch = 0;

    // ---- build CSR of S (warp per row, ballot compaction: deterministic order) ----
    for (int m = wg; m < NNODES; m += GWARPS){
        int cnt = 0;
        for (int c0 = 0; c0 < NNODES; c0 += 32){
            int c = c0 + lane;
            float v = (c < NNODES) ? S[m*NNODES + c] : 0.f;
            unsigned msk = __ballot_sync(0xffffffffu, v != 0.f);
            if (v != 0.f) g_s1[m*PADW + cnt + __popc(msk & ((1u<<lane)-1))] = packe(c, v);
            cnt += __popc(msk);
        }
        if (lane == 0) g_cnt1[m] = cnt;
    }
    // zero states
    for (int i = blockIdx.x*NTH + tid; i < NB*UNITS; i += GRID*NTH){
        g_h0[i] = 0.f; g_h1[i] = 0.f;
        if (i < NB) g_din[i] = 0.f;
    }
    gsync(epoch);

    // ---- build S2 = 2*S@S (warp per row; same math/order as validated R2 path) ----
    for (int m = wg; m < NNODES; m += GWARPS){
        int c1 = g_cnt1[m];
        int cnt = 0;
        for (int c0 = 0; c0 < NNODES; c0 += 32){
            int c = c0 + lane;
            float acc = 0.f;
            for (int j = 0; j < c1; j++){
                ull e = g_s1[m*PADW + j];
                int k = (int)(unsigned)e; float v = __uint_as_float((unsigned)(e>>32));
                if (c < NNODES) acc += v * S[k*NNODES + c];
            }
            acc *= 2.f;
            bool nz = (c < NNODES) && (acc != 0.f);
            unsigned msk = __ballot_sync(0xffffffffu, nz);
            if (nz) g_s2[m*PADW + cnt + __popc(msk & ((1u<<lane)-1))] = packe(c, acc);
            cnt += __popc(msk);
        }
        if (lane == 0) g_cnt2[m] = cnt;
    }
    gsync(epoch);

    // ---- encoder ----
    for (int t = 0; t < TSTEPS; t++){
        const float* inp_t = inputs + (size_t)t * BATCH * NNODES * DIN;
        run_cell(2, DIN,   0, inp_t,  e0gW, e0gb, e0cW, e0cb, 1,
                 nullptr, nullptr, nullptr, epoch, tid, wg, lane, As, Bs);
        run_cell(0, UNITS, 1, nullptr, e1gW, e1gb, e1cW, e1cb, 1,
                 nullptr, nullptr, nullptr, epoch, tid, wg, lane, As, Bs);
    }
    // ---- decoder ----
    for (int t = 0; t < HORIZON; t++){
        run_cell(1, 1,     0, nullptr, d0gW, d0gb, d0cW, d0cb, 1,
                 nullptr, nullptr, nullptr, epoch, tid, wg, lane, As, Bs);
        run_cell(0, UNITS, 1, nullptr, d1gW, d1gb, d1cW, d1cb, 2,
                 pW, pb, out + (size_t)t * BATCH * NNODES, epoch, tid, wg, lane, As, Bs);
    }
}

extern "C" void kernel_launch(void* const* d_in, const int* in_sizes, int n_in,
                              void* d_out, int out_size)
{
    const float* inputs  = (const float*)d_in[0];
    const float* support = (const float*)d_in[1];
    const float* e0gW = (const float*)d_in[2];  const float* e0gb = (const float*)d_in[3];
    const float* e0cW = (const float*)d_in[4];  const float* e0cb = (const float*)d_in[5];
    const float* e1gW = (const float*)d_in[6];  const float* e1gb = (const float*)d_in[7];
    const float* e1cW = (const float*)d_in[8];  const float* e1cb = (const float*)d_in[9];
    const float* d0gW = (const float*)d_in[10]; const float* d0gb = (const float*)d_in[11];
    const float* d0cW = (const float*)d_in[12]; const float* d0cb = (const float*)d_in[13];
    const float* d1gW = (const float*)d_in[14]; const float* d1gb = (const float*)d_in[15];
    const float* d1cW = (const float*)d_in[16]; const float* d1cb = (const float*)d_in[17];
    const float* pW   = (const float*)d_in[18]; const float* pb   = (const float*)d_in[19];
    float* out = (float*)d_out;

    init_bar<<<1, 1>>>();
    dcrnn_persistent<<<GRID, NTH>>>(inputs, support,
        e0gW, e0gb, e0cW, e0cb, e1gW, e1gb, e1cW, e1cb,
        d0gW, d0gb, d0cW, d0cb, d1gW, d1gb, d1cW, d1cb,
        pW, pb, out);
}

// round 7
// speedup vs baseline: 1.9840x; 1.9840x over previous
#include <cuda_runtime.h>
#include <cuda_bf16.h>
#include <math.h>

// ---------------- problem constants ----------------
#define NNODES 325
#define BATCH  64
#define TSTEPS 12
#define HORIZON 12
#define UNITS  64
#define DIN    2
#define NB (NNODES*BATCH)        // 20800 rows
#define F3MAX 384
#define MAXNNZ 110000

// ---------------- device scratch (no allocs allowed) ----------------
__device__ float g_h0[NB*UNITS];
__device__ float g_h1[NB*UNITS];
__device__ float g_din[NB];
__device__ float g_rh[NB*UNITS];      // r*h from gate epilogue
__device__ float g_xk[NB*F3MAX];      // row stride = F3 of current cell
__device__ float g_ru[NB*2*UNITS];    // u gate stored at cols [64,128)
__device__ int   g_rowptr[NNODES+1];
__device__ int   g_cols[MAXNNZ];
__device__ float g_vals[MAXNNZ];
__device__ int   g_cnt2[NNODES];
__device__ int   g_cols2[NNODES*NNODES];
__device__ float g_vals2[NNODES*NNODES];

// ---------------- CSR build of S (proven R1) ----------------
__global__ void build_csr(const float* __restrict__ S){
    __shared__ int cnt[NNODES+1];
    int t = threadIdx.x;
    for (int r = t; r < NNODES; r += blockDim.x){
        int c = 0;
        for (int j = 0; j < NNODES; j++) c += (S[r*NNODES + j] != 0.0f);
        cnt[r] = c;
    }
    __syncthreads();
    if (t == 0){
        int acc = 0;
        for (int r = 0; r < NNODES; r++){ int c = cnt[r]; cnt[r] = acc; acc += c; }
        cnt[NNODES] = acc;
    }
    __syncthreads();
    for (int r = t; r <= NNODES; r += blockDim.x) g_rowptr[r] = cnt[r];
    for (int r = t; r < NNODES; r += blockDim.x){
        int p = cnt[r];
        for (int j = 0; j < NNODES; j++){
            float v = S[r*NNODES + j];
            if (v != 0.0f){ g_cols[p] = j; g_vals[p] = v; p++; }
        }
    }
}

// ---------------- S2 = 2*S@S padded CSR (proven R2 numerics) ----------------
__global__ void build_s2(const float* __restrict__ S){
    __shared__ float rowv[NNODES];
    int m = blockIdx.x;
    int p0 = g_rowptr[m], p1 = g_rowptr[m+1];
    for (int c = threadIdx.x; c < NNODES; c += blockDim.x){
        float acc = 0.f;
        for (int j = p0; j < p1; j++)
            acc += g_vals[j] * S[g_cols[j]*NNODES + c];
        rowv[c] = 2.f*acc;
    }
    __syncthreads();
    if (threadIdx.x == 0){
        int c2 = 0;
        for (int c = 0; c < NNODES; c++){
            float v = rowv[c];
            if (v != 0.f){ g_cols2[m*NNODES + c2] = c; g_vals2[m*NNODES + c2] = v; c2++; }
        }
        g_cnt2[m] = c2;
    }
}

__global__ void zero_state(){
    int i = blockIdx.x*blockDim.x + threadIdx.x;
    if (i < NB*UNITS){ g_h0[i] = 0.f; g_h1[i] = 0.f; }
    if (i < NB) g_din[i] = 0.f;
}

// ---------------- fused concat + Chebyshev diffusion (flat, R1-style parallelism) ----------------
// phase 0 (gate): x0=[x,h] -> g_xk[0:F); x1=S x0 -> [F,2F); x2=S2 x0 - x0 -> [2F,3F)
// phase 1 (cand): src = g_rh; writes rh into [Fx,F), S rh into [F+Fx,2F), S2 rh - rh into [2F+Fx,3F)
__global__ __launch_bounds__(256)
void gconv_flat(int phase, int xsel /*0:h0 1:din 2:inp*/, int Fx, int hsel,
                const float* __restrict__ inp_t)
{
    const int F = Fx + UNITS, F3v = 3*F;
    const int ncols = phase ? UNITS : F;
    const int m = blockIdx.y;
    int c = blockIdx.x*256 + threadIdx.x;
    if (c >= BATCH*ncols) return;
    int b = c / ncols, f = c % ncols;
    const float* H = hsel ? g_h1 : g_h0;

    // source value at node k
    #define SRCV(k) ({                                                        \
        int rb = (k)*BATCH + b; float _v;                                     \
        if (phase)            _v = g_rh[rb*UNITS + f];                        \
        else if (f < Fx)      _v = (xsel == 2) ? inp_t[b*(NNODES*DIN) + (k)*DIN + f] \
                                   : ((xsel == 1) ? g_din[rb] : g_h0[rb*UNITS + f]); \
        else                  _v = H[rb*UNITS + (f - Fx)];                    \
        _v; })

    float own = SRCV(m);
    float a1 = 0.f;
    int p0 = g_rowptr[m], p1 = g_rowptr[m+1];
    #pragma unroll 4
    for (int j = p0; j < p1; j++)
        a1 += g_vals[j] * SRCV(g_cols[j]);
    float a2 = 0.f;
    int c2 = g_cnt2[m];
    const int*   cp = g_cols2 + m*NNODES;
    const float* vp = g_vals2 + m*NNODES;
    #pragma unroll 4
    for (int j = 0; j < c2; j++)
        a2 += vp[j] * SRCV(cp[j]);
    a2 -= own;
    #undef SRCV

    int orow = (m*BATCH + b)*F3v;
    int woff = phase ? Fx : 0;
    g_xk[orow + woff + f]       = own;
    g_xk[orow + F + woff + f]   = a1;
    g_xk[orow + 2*F + woff + f] = a2;
}

// ---------------- bf16-split tensor-core GEMM with fused GRU epilogues ----------------
// C = g_xk(NB x F3) @ W(F3 x WN) + bias, computed as AhBh + AhBl + AlBh in fp32.
// BM=128 rows per block, BN=64 cols (gate uses grid.y=2 for its 128 cols).
// epi 0 (gate): s=sigmoid(v); ng<64: g_rh[r][ng]=s*H[r][ng]; ng>=64: g_ru[r][ng]=s
// epi 1 (cand): c=tanh(v); H[r][n] = u*H + (1-u)*c
#define ASTR 24   // smem k-stride in bf16 (16 data + 8 pad) -> conflict-free frag reads

__device__ __forceinline__ void mma16816(float* d, const unsigned* a, const unsigned* b){
    asm volatile("mma.sync.aligned.m16n8k16.row.col.f32.bf16.bf16.f32 "
        "{%0,%1,%2,%3}, {%4,%5,%6,%7}, {%8,%9}, {%0,%1,%2,%3};"
        : "+f"(d[0]), "+f"(d[1]), "+f"(d[2]), "+f"(d[3])
        : "r"(a[0]), "r"(a[1]), "r"(a[2]), "r"(a[3]), "r"(b[0]), "r"(b[1]));
}
__device__ __forceinline__ void bfsplit(float a, __nv_bfloat16 &h, __nv_bfloat16 &l){
    h = __float2bfloat16(a);
    l = __float2bfloat16(a - __bfloat162float(h));
}

__global__ __launch_bounds__(256, 2)
void gemm_mma(int F3v, const float* __restrict__ W, int WN,
              const float* __restrict__ bias, int hsel, int epi)
{
    __shared__ __nv_bfloat16 As_hi[128*ASTR], As_lo[128*ASTR];
    __shared__ __nv_bfloat16 Bs_hi[64*ASTR],  Bs_lo[64*ASTR];

    float* H = hsel ? g_h1 : g_h0;
    const int tid  = threadIdx.x;
    const int lane = tid & 31, warp = tid >> 5;
    const int mw = warp & 3, nw = warp >> 2;     // 4x2 warp grid, warp tile 32x32
    const int g = lane >> 2, q = lane & 3;
    const int row0 = blockIdx.x*128;
    const int nbase = blockIdx.y*64;

    float acc[2][4][4];
    #pragma unroll
    for (int i = 0; i < 2; i++)
        #pragma unroll
        for (int j = 0; j < 4; j++)
            #pragma unroll
            for (int k = 0; k < 4; k++) acc[i][j][k] = 0.f;

    const int ktiles = (F3v + 15)/16;
    for (int kt = 0; kt < ktiles; kt++){
        int k0 = kt*16;
        // stage A (128 x 16): thread -> row=tid>>1, 8 consecutive k
        {
            int row = tid >> 1, kseg = (tid & 1)*8;
            int r = row0 + row;
            #pragma unroll
            for (int j = 0; j < 8; j++){
                int k = k0 + kseg + j;
                float a = (r < NB && k < F3v) ? g_xk[r*F3v + k] : 0.f;
                __nv_bfloat16 h, l; bfsplit(a, h, l);
                As_hi[row*ASTR + kseg + j] = h;
                As_lo[row*ASTR + kseg + j] = l;
            }
        }
        // stage B transposed (64 cols x 16 k): thread -> n=tid&63, k strided by 4
        {
            int n = tid & 63, kk0 = tid >> 6;
            #pragma unroll
            for (int kk = 0; kk < 4; kk++){
                int krow = kk0 + kk*4;
                int k = k0 + krow;
                float w = (k < F3v) ? W[k*WN + nbase + n] : 0.f;
                __nv_bfloat16 h, l; bfsplit(w, h, l);
                Bs_hi[n*ASTR + krow] = h;
                Bs_lo[n*ASTR + krow] = l;
            }
        }
        __syncthreads();

        unsigned aH[2][4], aL[2][4], bH[4][2], bL[4][2];
        #pragma unroll
        for (int ma = 0; ma < 2; ma++){
            int r = mw*32 + ma*16 + g;
            const unsigned* p0h = (const unsigned*)&As_hi[r*ASTR + q*2];
            const unsigned* p1h = (const unsigned*)&As_hi[(r+8)*ASTR + q*2];
            const unsigned* p0l = (const unsigned*)&As_lo[r*ASTR + q*2];
            const unsigned* p1l = (const unsigned*)&As_lo[(r+8)*ASTR + q*2];
            aH[ma][0] = p0h[0]; aH[ma][1] = p1h[0]; aH[ma][2] = p0h[4]; aH[ma][3] = p1h[4];
            aL[ma][0] = p0l[0]; aL[ma][1] = p1l[0]; aL[ma][2] = p0l[4]; aL[ma][3] = p1l[4];
        }
        #pragma unroll
        for (int na = 0; na < 4; na++){
            int cN = nw*32 + na*8 + g;
            const unsigned* pbh = (const unsigned*)&Bs_hi[cN*ASTR + q*2];
            const unsigned* pbl = (const unsigned*)&Bs_lo[cN*ASTR + q*2];
            bH[na][0] = pbh[0]; bH[na][1] = pbh[4];
            bL[na][0] = pbl[0]; bL[na][1] = pbl[4];
        }
        #pragma unroll
        for (int ma = 0; ma < 2; ma++)
            #pragma unroll
            for (int na = 0; na < 4; na++){
                mma16816(acc[ma][na], aH[ma], bH[na]);
                mma16816(acc[ma][na], aH[ma], bL[na]);
                mma16816(acc[ma][na], aL[ma], bH[na]);
            }
        __syncthreads();
    }

    // epilogue: lane holds (rA,n),(rA,n+1),(rB,n),(rB,n+1) per atom
    #pragma unroll
    for (int ma = 0; ma < 2; ma++){
        #pragma unroll
        for (int na = 0; na < 4; na++){
            int nloc = nw*32 + na*8 + q*2;
            int ng = nbase + nloc;
            #pragma unroll
            for (int e = 0; e < 4; e++){
                int r = row0 + mw*32 + ma*16 + g + ((e >= 2) ? 8 : 0);
                int n = ng + (e & 1);
                if (r >= NB) continue;
                float v = acc[ma][na][e] + bias[n];
                if (epi == 0){
                    float s = 1.f/(1.f + expf(-v));
                    if (n < UNITS) g_rh[r*UNITS + n] = s * H[r*UNITS + n];
                    else           g_ru[r*(2*UNITS) + n] = s;
                } else {
                    float cc = tanhf(v);
                    float u  = g_ru[r*(2*UNITS) + UNITS + n];
                    float h  = H[r*UNITS + n];
                    H[r*UNITS + n] = u*h + (1.f - u)*cc;
                }
            }
        }
    }
}

// ---------------- projection (proven R1) ----------------
__global__ void proj_kernel(const float* __restrict__ pW, const float* __restrict__ pb,
                            float* __restrict__ out_t){
    int nb = blockIdx.x*8 + threadIdx.y;
    int lane = threadIdx.x;
    float v = g_h1[nb*UNITS + lane]      * pW[lane]
            + g_h1[nb*UNITS + 32 + lane] * pW[32 + lane];
    #pragma unroll
    for (int o = 16; o > 0; o >>= 1) v += __shfl_down_sync(0xffffffffu, v, o);
    if (lane == 0){
        v += pb[0];
        int n = nb / BATCH, b = nb % BATCH;
        out_t[b*NNODES + n] = v;
        g_din[nb] = v;
    }
}

// ---------------- host-side cell orchestration ----------------
static void launch_cell(const float* inp_t, int xsel, int Fx, int hsel,
                        const float* gW, const float* gb,
                        const float* cW, const float* cb)
{
    int F = Fx + UNITS, F3v = 3*F;
    int gblocks = (BATCH*F + 255)/256;
    // gate gconv: concat + x1 + x2 fused
    gconv_flat<<<dim3(gblocks, NNODES), 256>>>(0, xsel, Fx, hsel, inp_t);
    // gate GEMM (128 cols via grid.y=2): writes g_rh (r*h) and g_ru (u)
    gemm_mma<<<dim3((NB + 127)/128, 2), 256>>>(F3v, gW, 2*UNITS, gb, hsel, 0);
    // cand gconv: rh diffusion into h-subcolumns
    gconv_flat<<<dim3((BATCH*UNITS + 255)/256, NNODES), 256>>>(1, xsel, Fx, hsel, nullptr);
    // cand GEMM: tanh + GRU combine, in-place H update
    gemm_mma<<<dim3((NB + 127)/128, 1), 256>>>(F3v, cW, UNITS, cb, hsel, 1);
}

extern "C" void kernel_launch(void* const* d_in, const int* in_sizes, int n_in,
                              void* d_out, int out_size)
{
    const float* inputs  = (const float*)d_in[0];
    const float* support = (const float*)d_in[1];
    const float* e0gW = (const float*)d_in[2];  const float* e0gb = (const float*)d_in[3];
    const float* e0cW = (const float*)d_in[4];  const float* e0cb = (const float*)d_in[5];
    const float* e1gW = (const float*)d_in[6];  const float* e1gb = (const float*)d_in[7];
    const float* e1cW = (const float*)d_in[8];  const float* e1cb = (const float*)d_in[9];
    const float* d0gW = (const float*)d_in[10]; const float* d0gb = (const float*)d_in[11];
    const float* d0cW = (const float*)d_in[12]; const float* d0cb = (const float*)d_in[13];
    const float* d1gW = (const float*)d_in[14]; const float* d1gb = (const float*)d_in[15];
    const float* d1cW = (const float*)d_in[16]; const float* d1cb = (const float*)d_in[17];
    const float* pW   = (const float*)d_in[18]; const float* pb   = (const float*)d_in[19];
    float* out = (float*)d_out;

    build_csr<<<1, 352>>>(support);
    build_s2<<<NNODES, 325>>>(support);
    zero_state<<<(NB*UNITS + 255)/256, 256>>>();

    for (int t = 0; t < TSTEPS; t++){
        const float* inp_t = inputs + (size_t)t * BATCH * NNODES * DIN;
        launch_cell(inp_t,  2, DIN,   0, e0gW, e0gb, e0cW, e0cb);
        launch_cell(nullptr,0, UNITS, 1, e1gW, e1gb, e1cW, e1cb);
    }
    for (int t = 0; t < HORIZON; t++){
        launch_cell(nullptr, 1, 1,     0, d0gW, d0gb, d0cW, d0cb);
        launch_cell(nullptr, 0, UNITS, 1, d1gW, d1gb, d1cW, d1cb);
        proj_kernel<<<NB/8, dim3(32, 8)>>>(pW, pb, out + (size_t)t * BATCH * NNODES);
    }
}

// round 8
// speedup vs baseline: 2.0423x; 1.0294x over previous
#include <cuda_runtime.h>
#include <cuda_bf16.h>
#include <math.h>

// ---------------- problem constants ----------------
#define NNODES 325
#define BATCH  64
#define TSTEPS 12
#define HORIZON 12
#define UNITS  64
#define DIN    2
#define NB (NNODES*BATCH)        // 20800
#define F3MAX 384
#define PADW 352
#define GRID 148                 // <= SM count, 1 CTA/SM -> all resident -> spin barrier safe
#define NTH  512
#define ASTR 24                  // smem k-stride (bf16), conflict-benign, proven R7
#define WPMAX (16*24*64)         // max frag-packed words per matrix (gate, F3=384)

typedef unsigned long long ull;

// ---------------- device scratch ----------------
__device__ float g_h0[NB*UNITS];
__device__ float g_h1[NB*UNITS];
__device__ float g_din[NB];
__device__ float g_rh[NB*UNITS];
__device__ float g_xk[NB*F3MAX];
__device__ float g_ru[NB*2*UNITS];
__device__ int   g_cnt1[NNODES];
__device__ ull   g_s1[NNODES*PADW];      // packed (col,val) CSR of S
__device__ unsigned g_wph[8][WPMAX];     // frag-packed folded weights, hi
__device__ unsigned g_wpl[8][WPMAX];     // frag-packed folded weights, lo
__device__ unsigned g_bar;

__global__ void init_bar(){ g_bar = 0u; }

// ---------------- helpers ----------------
__device__ __forceinline__ void bfsplit(float a, __nv_bfloat16 &h, __nv_bfloat16 &l){
    h = __float2bfloat16(a);
    l = __float2bfloat16(a - __bfloat162float(h));
}
__device__ __forceinline__ void mma16816(float* d, const unsigned* a, const unsigned* b){
    asm volatile("mma.sync.aligned.m16n8k16.row.col.f32.bf16.bf16.f32 "
        "{%0,%1,%2,%3}, {%4,%5,%6,%7}, {%8,%9}, {%0,%1,%2,%3};"
        : "+f"(d[0]), "+f"(d[1]), "+f"(d[2]), "+f"(d[3])
        : "r"(a[0]), "r"(a[1]), "r"(a[2]), "r"(a[3]), "r"(b[0]), "r"(b[1]));
}

// grid barrier (R3-proven): monotonic counter, all CTAs resident.
__device__ __forceinline__ void gsync(unsigned &epoch){
    __threadfence();
    __syncthreads();
    if (threadIdx.x == 0){
        epoch += GRID;
        atomicAdd(&g_bar, 1u);
        while (*(volatile unsigned*)&g_bar < epoch) { }
    }
    __syncthreads();
    __threadfence();
}

// ---------------- setup kernels ----------------
// packed CSR of S via warp ballot (deterministic order)
__global__ void build_csr_pk(const float* __restrict__ S){
    int m = blockIdx.x, lane = threadIdx.x;
    int cnt = 0;
    for (int c0 = 0; c0 < NNODES; c0 += 32){
        int c = c0 + lane;
        float v = (c < NNODES) ? S[m*NNODES + c] : 0.f;
        unsigned msk = __ballot_sync(0xffffffffu, v != 0.f);
        if (v != 0.f)
            g_s1[m*PADW + cnt + __popc(msk & ((1u<<lane)-1))] =
                ((ull)__float_as_uint(v) << 32) | (unsigned)c;
        cnt += __popc(msk);
    }
    if (lane == 0) g_cnt1[m] = cnt;
}

__global__ void zero_state(){
    int i = blockIdx.x*blockDim.x + threadIdx.x;
    if (i < NB*UNITS){ g_h0[i] = 0.f; g_h1[i] = 0.f; }
    if (i < NB) g_din[i] = 0.f;
}

// folded weight: basis [x0, Sx0, S(Sx0)] -> W' = [W0 - W2 ; W1 ; 2*W2]
__device__ __forceinline__ float wmod_val(const float* W, int F, int F3v, int ONUM, int k, int n){
    if (k >= F3v) return 0.f;
    if (k < F)    return W[k*ONUM + n] - W[(2*F + k)*ONUM + n];
    if (k < 2*F)  return W[k*ONUM + n];
    return 2.f*W[k*ONUM + n];
}
// pack folded weights into m16n8k16 B-fragment order (mapping proven in R7 loader)
__global__ void prep_w(const float* __restrict__ W, int F, int ONUM, int mat){
    int F3v = 3*F, NKT = (F3v + 15)/16, NB8 = ONUM/8;
    int total = NB8*NKT*64;
    for (int idx = blockIdx.x*blockDim.x + threadIdx.x; idx < total; idx += gridDim.x*blockDim.x){
        int reg = idx & 1, lane = (idx >> 1) & 31;
        int t2 = idx >> 6; int kt = t2 % NKT, nb8 = t2 / NKT;
        int gg = lane >> 2, qq = lane & 3;
        int n  = nb8*8 + gg;
        int k0 = kt*16 + qq*2 + reg*8;
        float w0 = wmod_val(W, F, F3v, ONUM, k0,     n);
        float w1 = wmod_val(W, F, F3v, ONUM, k0 + 1, n);
        __nv_bfloat16 h0,l0,h1,l1; bfsplit(w0,h0,l0); bfsplit(w1,h1,l1);
        g_wph[mat][idx] = (unsigned)__bfloat16_as_ushort(h0) | ((unsigned)__bfloat16_as_ushort(h1) << 16);
        g_wpl[mat][idx] = (unsigned)__bfloat16_as_ushort(l0) | ((unsigned)__bfloat16_as_ushort(l1) << 16);
    }
}

// ---------------- sparse diffusion phases (flat, coalesced, R7-style) ----------------
// mode 0: x0=[x,h] -> xk[0:F), S x0 -> xk[F,2F)
// mode 1: S x1 -> xk[2F,3F)                         (cheb combine folded into W')
// mode 2: rh -> xk[Fx..F), S rh -> xk[F+Fx..2F)
// mode 3: S (S rh) -> xk[2F+Fx..3F)
__device__ void sp_phase(int mode, int Fx, int hsel, int xsel, const float* __restrict__ inp_t){
    const int F = Fx + UNITS, F3v = 3*F;
    const int ncols = (mode <= 1) ? F : UNITS;
    const int total = BATCH*ncols;
    const int nch = (total + NTH - 1)/NTH;
    const int ntasks = NNODES*nch;
    const float* H = hsel ? g_h1 : g_h0;

    for (int t = blockIdx.x; t < ntasks; t += GRID){
        int m = t / nch, ch = t - m*nch;
        int c = ch*NTH + (int)threadIdx.x;
        if (c >= total) continue;
        int b = c / ncols, f = c - b*ncols;

        auto src = [&](int k)->float{
            int rb = k*BATCH + b;
            if (mode == 1) return g_xk[rb*F3v + F + f];
            if (mode == 2) return g_rh[rb*UNITS + f];
            if (mode == 3) return g_xk[rb*F3v + F + Fx + f];
            if (f < Fx){
                if (xsel == 2) return inp_t[b*(NNODES*DIN) + k*DIN + f];
                if (xsel == 1) return g_din[rb];
                return g_h0[rb*UNITS + f];
            }
            return H[rb*UNITS + (f - Fx)];
        };

        int cnt = g_cnt1[m];
        const ull* e = g_s1 + m*PADW;
        float s0 = 0.f, s1v = 0.f;
        int j = 0;
        for (; j + 1 < cnt; j += 2){
            ull e0 = e[j], e1 = e[j+1];
            int k0 = (int)(unsigned)e0; float v0 = __uint_as_float((unsigned)(e0 >> 32));
            int k1 = (int)(unsigned)e1; float v1 = __uint_as_float((unsigned)(e1 >> 32));
            s0  += v0*src(k0);
            s1v += v1*src(k1);
        }
        if (j < cnt){
            ull e0 = e[j];
            int k0 = (int)(unsigned)e0; float v0 = __uint_as_float((unsigned)(e0 >> 32));
            s0 += v0*src(k0);
        }
        float a1 = s0 + s1v;
        int orow = (m*BATCH + b)*F3v;
        if      (mode == 0){ g_xk[orow + f] = src(m); g_xk[orow + F + f] = a1; }
        else if (mode == 1){ g_xk[orow + 2*F + f] = a1; }
        else if (mode == 2){ g_xk[orow + Fx + f] = g_rh[(m*BATCH + b)*UNITS + f];
                             g_xk[orow + F + Fx + f] = a1; }
        else               { g_xk[orow + 2*F + Fx + f] = a1; }
    }
}

// ---------------- mma GEMM phase (frag mapping proven in R7) ----------------
// epi 0 (gate): s=sigmoid(v); n<64 -> g_rh = s*H ; n>=64 -> g_ru = s
// epi 1 (cand): c=tanh(v); H = u*H + (1-u)*c
// epi 2: epi1 + fused projection (deterministic shfl+smem reduce) -> out_t, g_din
template<int MW, int NW, int ONUM>
__device__ void gemm_phase(int F3v, int NKT,
                           const unsigned* __restrict__ wph, const unsigned* __restrict__ wpl,
                           const float* __restrict__ bias, int hsel, int epi,
                           const float* __restrict__ pW, const float* __restrict__ pb,
                           float* __restrict__ out_t,
                           __nv_bfloat16* As_hi, __nv_bfloat16* As_lo, float* smem_p)
{
    const int BM = MW*32;
    const int NA = ONUM/(8*NW);                 // = 4 for both configs
    const int NTILES = (NB + BM - 1)/BM;
    float* H = hsel ? g_h1 : g_h0;

    const int tid = threadIdx.x;
    const int lane = tid & 31, wid = tid >> 5;
    const int mw = wid % MW, nw = wid / MW;
    const int g = lane >> 2, q = lane & 3;
    const int EPT = (BM*16)/NTH;                // 4 or 8 elems/thread for A staging
    const int TPR = 16/EPT;
    const int srow = tid / TPR, skb = (tid % TPR)*EPT;

    for (int tile = blockIdx.x; tile < NTILES; tile += GRID){
        int row0 = tile*BM;
        float acc[2][NA][4];
        #pragma unroll
        for (int i = 0; i < 2; i++)
            #pragma unroll
            for (int j = 0; j < NA; j++)
                #pragma unroll
                for (int k = 0; k < 4; k++) acc[i][j][k] = 0.f;

        for (int kt = 0; kt < NKT; kt++){
            // stage A tile (runtime bf16 split)
            {
                int r = row0 + srow;
                #pragma unroll
                for (int jj = 0; jj < EPT; jj++){
                    int k = kt*16 + skb + jj;
                    float a = (r < NB && k < F3v) ? g_xk[r*F3v + k] : 0.f;
                    __nv_bfloat16 h, l; bfsplit(a, h, l);
                    As_hi[srow*ASTR + skb + jj] = h;
                    As_lo[srow*ASTR + skb + jj] = l;
                }
            }
            __syncthreads();

            unsigned aH[2][4], aL[2][4];
            #pragma unroll
            for (int ma = 0; ma < 2; ma++){
                int rr = mw*32 + ma*16 + g;
                const unsigned* p0h = (const unsigned*)&As_hi[rr*ASTR + q*2];
                const unsigned* p1h = (const unsigned*)&As_hi[(rr+8)*ASTR + q*2];
                const unsigned* p0l = (const unsigned*)&As_lo[rr*ASTR + q*2];
                const unsigned* p1l = (const unsigned*)&As_lo[(rr+8)*ASTR + q*2];
                aH[ma][0]=p0h[0]; aH[ma][1]=p1h[0]; aH[ma][2]=p0h[4]; aH[ma][3]=p1h[4];
                aL[ma][0]=p0l[0]; aL[ma][1]=p1l[0]; aL[ma][2]=p0l[4]; aL[ma][3]=p1l[4];
            }
            #pragma unroll
            for (int na = 0; na < NA; na++){
                int nb8 = nw*NA + na;
                uint2 bh = *(const uint2*)(wph + ((nb8*NKT + kt)*32 + lane)*2);
                uint2 bl = *(const uint2*)(wpl + ((nb8*NKT + kt)*32 + lane)*2);
                unsigned bH[2] = {bh.x, bh.y}, bL[2] = {bl.x, bl.y};
                #pragma unroll
                for (int ma = 0; ma < 2; ma++){
                    mma16816(acc[ma][na], aH[ma], bH);
                    mma16816(acc[ma][na], aH[ma], bL);
                    mma16816(acc[ma][na], aL[ma], bH);
                }
            }
            __syncthreads();
        }

        // epilogue
        float pvp[2][2] = {{0.f,0.f},{0.f,0.f}};
        #pragma unroll
        for (int ma = 0; ma < 2; ma++){
            #pragma unroll
            for (int na = 0; na < NA; na++){
                int nb = nw*(8*NA) + na*8 + q*2;
                #pragma unroll
                for (int e = 0; e < 4; e++){
                    int r = row0 + mw*32 + ma*16 + g + ((e >= 2) ? 8 : 0);
                    int n = nb + (e & 1);
                    if (r >= NB) continue;
                    float v = acc[ma][na][e] + bias[n];
                    if (epi == 0){
                        float s = 1.f/(1.f + expf(-v));
                        if (n < UNITS) g_rh[r*UNITS + n] = s * H[r*UNITS + n];
                        else           g_ru[r*(2*UNITS) + n] = s;
                    } else {
                        float cc = tanhf(v);
                        float u  = g_ru[r*(2*UNITS) + UNITS + n];
                        float h  = H[r*UNITS + n];
                        float hn = u*h + (1.f - u)*cc;
                        H[r*UNITS + n] = hn;
                        if (epi == 2) pvp[ma][e >> 1] += hn * pW[n];
                    }
                }
            }
        }
        if (epi == 2){
            #pragma unroll
            for (int ma = 0; ma < 2; ma++)
                #pragma unroll
                for (int eh = 0; eh < 2; eh++){
                    float v = pvp[ma][eh];
                    v += __shfl_down_sync(0xffffffffu, v, 2);
                    v += __shfl_down_sync(0xffffffffu, v, 1);
                    if (q == 0){
                        int rl = mw*32 + ma*16 + g + 8*eh;
                        smem_p[rl*NW + nw] = v;
                    }
                }
            __syncthreads();
            if (tid < BM){
                int rl = tid, r = row0 + rl;
                if (r < NB){
                    float v = pb[0];
                    #pragma unroll
                    for (int w2 = 0; w2 < NW; w2++) v += smem_p[rl*NW + w2];
                    g_din[r] = v;
                    out_t[(r & 63)*NNODES + (r >> 6)] = v;
                }
            }
            __syncthreads();
        }
    }
}

// ---------------- one GRU cell ----------------
__device__ void run_cell(int xsel, int Fx, int hsel, const float* inp_t,
                         int matg, int matc,
                         const float* gb, const float* cb, int cand_epi,
                         const float* pW, const float* pb, float* out_t,
                         unsigned &epoch,
                         __nv_bfloat16* As_hi, __nv_bfloat16* As_lo, float* smem_p)
{
    int F = Fx + UNITS, F3v = 3*F, NKT = (F3v + 15)/16;
    sp_phase(0, Fx, hsel, xsel, inp_t);  gsync(epoch);
    sp_phase(1, Fx, hsel, xsel, nullptr); gsync(epoch);
    gemm_phase<4,4,128>(F3v, NKT, g_wph[matg], g_wpl[matg], gb, hsel, 0,
                        nullptr, nullptr, nullptr, As_hi, As_lo, smem_p); gsync(epoch);
    sp_phase(2, Fx, hsel, xsel, nullptr); gsync(epoch);
    sp_phase(3, Fx, hsel, xsel, nullptr); gsync(epoch);
    gemm_phase<8,2,64>(F3v, NKT, g_wph[matc], g_wpl[matc], cb, hsel, cand_epi,
                       pW, pb, out_t, As_hi, As_lo, smem_p); gsync(epoch);
}

// ---------------- the whole network, one launch ----------------
__global__ void __launch_bounds__(NTH, 1)
dcrnn_pers(const float* __restrict__ inputs,
           const float* e0gb, const float* e0cb,
           const float* e1gb, const float* e1cb,
           const float* d0gb, const float* d0cb,
           const float* d1gb, const float* d1cb,
           const float* pW, const float* pb, float* __restrict__ out)
{
    __shared__ __nv_bfloat16 As_hi[256*ASTR], As_lo[256*ASTR];   // 24 KB
    __shared__ float smem_p[256*2];
    unsigned epoch = 0;

    for (int t = 0; t < TSTEPS; t++){
        const float* inp_t = inputs + (size_t)t * BATCH * NNODES * DIN;
        run_cell(2, DIN,   0, inp_t,   0, 4, e0gb, e0cb, 1, nullptr, nullptr, nullptr,
                 epoch, As_hi, As_lo, smem_p);
        run_cell(0, UNITS, 1, nullptr, 1, 5, e1gb, e1cb, 1, nullptr, nullptr, nullptr,
                 epoch, As_hi, As_lo, smem_p);
    }
    for (int t = 0; t < HORIZON; t++){
        run_cell(1, 1,     0, nullptr, 2, 6, d0gb, d0cb, 1, nullptr, nullptr, nullptr,
                 epoch, As_hi, As_lo, smem_p);
        run_cell(0, UNITS, 1, nullptr, 3, 7, d1gb, d1cb, 2, pW, pb,
                 out + (size_t)t * BATCH * NNODES,
                 epoch, As_hi, As_lo, smem_p);
    }
}

extern "C" void kernel_launch(void* const* d_in, const int* in_sizes, int n_in,
                              void* d_out, int out_size)
{
    const float* inputs  = (const float*)d_in[0];
    const float* support = (const float*)d_in[1];
    const float* e0gW = (const float*)d_in[2];  const float* e0gb = (const float*)d_in[3];
    const float* e0cW = (const float*)d_in[4];  const float* e0cb = (const float*)d_in[5];
    const float* e1gW = (const float*)d_in[6];  const float* e1gb = (const float*)d_in[7];
    const float* e1cW = (const float*)d_in[8];  const float* e1cb = (const float*)d_in[9];
    const float* d0gW = (const float*)d_in[10]; const float* d0gb = (const float*)d_in[11];
    const float* d0cW = (const float*)d_in[12]; const float* d0cb = (const float*)d_in[13];
    const float* d1gW = (const float*)d_in[14]; const float* d1gb = (const float*)d_in[15];
    const float* d1cW = (const float*)d_in[16]; const float* d1cb = (const float*)d_in[17];
    const float* pW   = (const float*)d_in[18]; const float* pb   = (const float*)d_in[19];
    float* out = (float*)d_out;

    init_bar<<<1, 1>>>();
    build_csr_pk<<<NNODES, 32>>>(support);
    zero_state<<<(NB*UNITS + 255)/256, 256>>>();
    // fold + fragment-pack weights (gate mats 0..3, cand mats 4..7)
    prep_w<<<64, 256>>>(e0gW, DIN + UNITS, 2*UNITS, 0);
    prep_w<<<64, 256>>>(e1gW, 2*UNITS,     2*UNITS, 1);
    prep_w<<<64, 256>>>(d0gW, 1 + UNITS,   2*UNITS, 2);
    prep_w<<<64, 256>>>(d1gW, 2*UNITS,     2*UNITS, 3);
    prep_w<<<64, 256>>>(e0cW, DIN + UNITS, UNITS,   4);
    prep_w<<<64, 256>>>(e1cW, 2*UNITS,     UNITS,   5);
    prep_w<<<64, 256>>>(d0cW, 1 + UNITS,   UNITS,   6);
    prep_w<<<64, 256>>>(d1cW, 2*UNITS,     UNITS,   7);

    dcrnn_pers<<<GRID, NTH>>>(inputs,
        e0gb, e0cb, e1gb, e1cb, d0gb, d0cb, d1gb, d1cb,
        pW, pb, out);
}

// round 9
// speedup vs baseline: 2.0794x; 1.0182x over previous
#include <cuda_runtime.h>
#include <cuda_bf16.h>
#include <math.h>

// ---------------- problem constants ----------------
#define NNODES 325
#define BATCH  64
#define TSTEPS 12
#define HORIZON 12
#define UNITS  64
#define DIN    2
#define MAXNNZ 110000
#define XKSTR  (NNODES*384)      // per-batch xk slice stride (floats), 16B-mult
#define NTH    512
#define ASTR   24                // smem k-stride (bf16), proven R7/R8
#define WPMAX  32768             // frag-packed words per matrix (max 16*24*64=24576)
#define MAXE   2600              // smem CSR cap (expected nnz ~2150)

typedef unsigned long long ull;

// ---------------- device scratch ----------------
__device__ __align__(16) float g_xk[BATCH*XKSTR];
__device__ float g_h0[BATCH*NNODES*UNITS];
__device__ float g_h1[BATCH*NNODES*UNITS];
__device__ float g_u [BATCH*NNODES*UNITS];
__device__ float g_din[BATCH*NNODES];
__device__ int   g_rowptr[NNODES+1];
__device__ int   g_cols[MAXNNZ];
__device__ float g_vals[MAXNNZ];
__device__ unsigned g_wph[8][WPMAX];
__device__ unsigned g_wpl[8][WPMAX];

// ---------------- helpers ----------------
__device__ __forceinline__ void bfsplit(float a, __nv_bfloat16 &h, __nv_bfloat16 &l){
    h = __float2bfloat16(a);
    l = __float2bfloat16(a - __bfloat162float(h));
}
__device__ __forceinline__ void mma16816(float* d, const unsigned* a, const unsigned* b){
    asm volatile("mma.sync.aligned.m16n8k16.row.col.f32.bf16.bf16.f32 "
        "{%0,%1,%2,%3}, {%4,%5,%6,%7}, {%8,%9}, {%0,%1,%2,%3};"
        : "+f"(d[0]), "+f"(d[1]), "+f"(d[2]), "+f"(d[3])
        : "r"(a[0]), "r"(a[1]), "r"(a[2]), "r"(a[3]), "r"(b[0]), "r"(b[1]));
}

// ---------------- setup: compact CSR of S (proven R1) ----------------
__global__ void build_csr(const float* __restrict__ S){
    __shared__ int cnt[NNODES+1];
    int t = threadIdx.x;
    for (int r = t; r < NNODES; r += blockDim.x){
        int c = 0;
        for (int j = 0; j < NNODES; j++) c += (S[r*NNODES + j] != 0.0f);
        cnt[r] = c;
    }
    __syncthreads();
    if (t == 0){
        int acc = 0;
        for (int r = 0; r < NNODES; r++){ int c = cnt[r]; cnt[r] = acc; acc += c; }
        cnt[NNODES] = acc;
    }
    __syncthreads();
    for (int r = t; r <= NNODES; r += blockDim.x) g_rowptr[r] = cnt[r];
    for (int r = t; r < NNODES; r += blockDim.x){
        int p = cnt[r];
        for (int j = 0; j < NNODES; j++){
            float v = S[r*NNODES + j];
            if (v != 0.0f){ g_cols[p] = j; g_vals[p] = v; p++; }
        }
    }
}

// ---------------- setup: folded + frag-packed weights (R8 mapping, sectioned) ----------------
// basis [x0, Sx0, SSx0], W' = [W0 - W2 ; W1 ; 2*W2], sections padded to FP
__device__ __forceinline__ float wmod(const float* W, int F, int FP, int ONUM, int k, int n){
    int sec = k / FP, col = k - sec*FP;
    if (sec > 2 || col >= F) return 0.f;
    if (sec == 0) return W[col*ONUM + n] - W[(2*F + col)*ONUM + n];
    if (sec == 1) return W[(F + col)*ONUM + n];
    return 2.f*W[(2*F + col)*ONUM + n];
}
__global__ void prep_w(const float* __restrict__ W, int F, int FP, int ONUM, int mat){
    int F3P = 3*FP, NKT = (F3P + 15)/16, NB8 = ONUM/8;
    int total = NB8*NKT*64;
    for (int idx = blockIdx.x*blockDim.x + threadIdx.x; idx < total; idx += gridDim.x*blockDim.x){
        int reg = idx & 1, lane = (idx >> 1) & 31;
        int t2 = idx >> 6; int kt = t2 % NKT, nb8 = t2 / NKT;
        int gg = lane >> 2, qq = lane & 3;
        int n  = nb8*8 + gg;
        int k0 = kt*16 + qq*2 + reg*8;
        float w0 = wmod(W, F, FP, ONUM, k0,     n);
        float w1 = wmod(W, F, FP, ONUM, k0 + 1, n);
        __nv_bfloat16 h0,l0,h1,l1; bfsplit(w0,h0,l0); bfsplit(w1,h1,l1);
        g_wph[mat][idx] = (unsigned)__bfloat16_as_ushort(h0) | ((unsigned)__bfloat16_as_ushort(h1) << 16);
        g_wpl[mat][idx] = (unsigned)__bfloat16_as_ushort(l0) | ((unsigned)__bfloat16_as_ushort(l1) << 16);
    }
}

// ---------------- sparse apply: dst[m][f] = sum_k S[m,k] src[k][f], float4 cols ----------------
template<int FP>
__device__ void sp_apply(float* xk, int src, int dst, int a0,
                         const ull* s_ent, const int* s_rp)
{
    const int F3P = 3*FP;
    const int G = (FP - a0) >> 2;
    const int tasks = NNODES*G;
    for (int t = threadIdx.x; t < tasks; t += NTH){
        int m = t / G, gi = t - m*G;
        int f = a0 + gi*4;
        const float* sp = xk + src + f;
        float ax = 0.f, ay = 0.f, az = 0.f, aw = 0.f;
        int j = s_rp[m], j1 = s_rp[m+1];
        for (; j + 1 < j1; j += 2){
            ull e0 = s_ent[j], e1 = s_ent[j+1];
            float v0 = __uint_as_float((unsigned)(e0 >> 32));
            float v1 = __uint_as_float((unsigned)(e1 >> 32));
            float4 x0 = *(const float4*)(sp + (int)(unsigned)e0 * F3P);
            float4 x1 = *(const float4*)(sp + (int)(unsigned)e1 * F3P);
            ax += v0*x0.x + v1*x1.x;  ay += v0*x0.y + v1*x1.y;
            az += v0*x0.z + v1*x1.z;  aw += v0*x0.w + v1*x1.w;
        }
        if (j < j1){
            ull e0 = s_ent[j];
            float v0 = __uint_as_float((unsigned)(e0 >> 32));
            float4 x0 = *(const float4*)(sp + (int)(unsigned)e0 * F3P);
            ax += v0*x0.x; ay += v0*x0.y; az += v0*x0.z; aw += v0*x0.w;
        }
        *(float4*)(xk + m*F3P + dst + f) = make_float4(ax, ay, az, aw);
    }
}

// ---------------- mma GEMM (R8 frag mapping verbatim), M=325 chunked ----------------
// epi 0 (gate): s=sigmoid(v); n<64 -> xk[r][FX+n]=s*H ; n>=64 -> us[r][n-64]=s
// epi 1 (cand): c=tanh(v); H = u*H + (1-u)*c
// epi 2: epi1 + fused projection -> out_t[r], din[r]
template<int MW, int NW, int ONUM, int FP>
__device__ void gemm_run(float* xk,
                         const unsigned* __restrict__ wph, const unsigned* __restrict__ wpl,
                         const float* __restrict__ bias, float* H, float* us, int epi, int FX,
                         const float* __restrict__ pW, const float* __restrict__ pb,
                         float* __restrict__ out_t, float* __restrict__ din,
                         __nv_bfloat16* As_hi, __nv_bfloat16* As_lo, float* s_red)
{
    const int F3P = 3*FP;
    const int NKT = (F3P + 15)/16;
    const int BM  = MW*32;
    const int NA  = ONUM/(8*NW);
    const int NCH = (NNODES + BM - 1)/BM;

    const int tid = threadIdx.x;
    const int lane = tid & 31, wid = tid >> 5;
    const int mw = wid % MW, nw = wid / MW;
    const int g = lane >> 2, q = lane & 3;
    const int EPT = (BM*16)/NTH;
    const int TPR = 16/EPT;
    const int srow = tid / TPR, skb = (tid % TPR)*EPT;

    for (int ch = 0; ch < NCH; ch++){
        int row0 = ch*BM;
        float acc[2][NA][4];
        #pragma unroll
        for (int i = 0; i < 2; i++)
            #pragma unroll
            for (int j = 0; j < NA; j++)
                #pragma unroll
                for (int k = 0; k < 4; k++) acc[i][j][k] = 0.f;

        for (int kt = 0; kt < NKT; kt++){
            {   // stage A (bf16 split)
                int r = row0 + srow;
                #pragma unroll
                for (int jj = 0; jj < EPT; jj++){
                    int k = kt*16 + skb + jj;
                    float a = (r < NNODES && k < F3P) ? xk[r*F3P + k] : 0.f;
                    __nv_bfloat16 h, l; bfsplit(a, h, l);
                    As_hi[srow*ASTR + skb + jj] = h;
                    As_lo[srow*ASTR + skb + jj] = l;
                }
            }
            __syncthreads();

            unsigned aH[2][4], aL[2][4];
            #pragma unroll
            for (int ma = 0; ma < 2; ma++){
                int rr = mw*32 + ma*16 + g;
                const unsigned* p0h = (const unsigned*)&As_hi[rr*ASTR + q*2];
                const unsigned* p1h = (const unsigned*)&As_hi[(rr+8)*ASTR + q*2];
                const unsigned* p0l = (const unsigned*)&As_lo[rr*ASTR + q*2];
                const unsigned* p1l = (const unsigned*)&As_lo[(rr+8)*ASTR + q*2];
                aH[ma][0]=p0h[0]; aH[ma][1]=p1h[0]; aH[ma][2]=p0h[4]; aH[ma][3]=p1h[4];
                aL[ma][0]=p0l[0]; aL[ma][1]=p1l[0]; aL[ma][2]=p0l[4]; aL[ma][3]=p1l[4];
            }
            #pragma unroll
            for (int na = 0; na < NA; na++){
                int nb8 = nw*NA + na;
                uint2 bh = *(const uint2*)(wph + ((nb8*NKT + kt)*32 + lane)*2);
                uint2 bl = *(const uint2*)(wpl + ((nb8*NKT + kt)*32 + lane)*2);
                unsigned bH[2] = {bh.x, bh.y}, bL[2] = {bl.x, bl.y};
                #pragma unroll
                for (int ma = 0; ma < 2; ma++){
                    mma16816(acc[ma][na], aH[ma], bH);
                    mma16816(acc[ma][na], aH[ma], bL);
                    mma16816(acc[ma][na], aL[ma], bH);
                }
            }
            __syncthreads();
        }

        // epilogue
        float pvp[2][2] = {{0.f,0.f},{0.f,0.f}};
        #pragma unroll
        for (int ma = 0; ma < 2; ma++){
            #pragma unroll
            for (int na = 0; na < NA; na++){
                int nb = nw*(8*NA) + na*8 + q*2;
                #pragma unroll
                for (int e = 0; e < 4; e++){
                    int r = row0 + mw*32 + ma*16 + g + ((e >= 2) ? 8 : 0);
                    int n = nb + (e & 1);
                    if (r >= NNODES) continue;
                    float v = acc[ma][na][e] + bias[n];
                    if (epi == 0){
                        float s = 1.f/(1.f + expf(-v));
                        if (n < UNITS) xk[r*F3P + FX + n] = s * H[r*UNITS + n];
                        else           us[r*UNITS + (n - UNITS)] = s;
                    } else {
                        float cc = tanhf(v);
                        float u  = us[r*UNITS + n];
                        float h  = H[r*UNITS + n];
                        float hn = u*h + (1.f - u)*cc;
                        H[r*UNITS + n] = hn;
                        if (epi == 2) pvp[ma][e >> 1] += hn * pW[n];
                    }
                }
            }
        }
        if (epi == 2){
            #pragma unroll
            for (int ma = 0; ma < 2; ma++)
                #pragma unroll
                for (int eh = 0; eh < 2; eh++){
                    float v = pvp[ma][eh];
                    v += __shfl_down_sync(0xffffffffu, v, 2);
                    v += __shfl_down_sync(0xffffffffu, v, 1);
                    if (q == 0) s_red[(mw*32 + ma*16 + g + 8*eh)*NW + nw] = v;
                }
            __syncthreads();
            if (tid < BM){
                int r = row0 + tid;
                if (r < NNODES){
                    float v = pb[0];
                    #pragma unroll
                    for (int w2 = 0; w2 < NW; w2++) v += s_red[tid*NW + w2];
                    din[r]  = v;
                    out_t[r] = v;
                }
            }
            __syncthreads();
        }
    }
}

// ---------------- one GRU cell (FX: 2=enc0-input, 1=dec0-din, 64=h0-input) ----------------
template<int FX, int F, int FP>
__device__ void cell_run(float* xk, const float* __restrict__ xptr,
                         float* H, float* us,
                         const unsigned* wgh, const unsigned* wgl, const float* gb,
                         const unsigned* wch, const unsigned* wcl, const float* cb,
                         int epi_cand, const float* pW, const float* pb,
                         float* out_t, float* din,
                         const ull* s_ent, const int* s_rp,
                         __nv_bfloat16* As_hi, __nv_bfloat16* As_lo, float* s_red)
{
    const int F3P = 3*FP;
    // A) concat x0=[x,h] + zero pads
    for (int idx = threadIdx.x; idx < NNODES*FP; idx += NTH){
        int m = idx / FP, f = idx - m*FP;
        float v;
        if (f >= F)      v = 0.f;
        else if (f < FX) v = (FX == 2) ? xptr[m*DIN + f]
                           : ((FX == 1) ? xptr[m] : xptr[m*UNITS + f]);
        else             v = H[m*UNITS + (f - FX)];
        xk[m*F3P + f] = v;
    }
    __syncthreads();
    sp_apply<FP>(xk, 0,  FP,   0, s_ent, s_rp);      // x1 = S x0
    __syncthreads();
    sp_apply<FP>(xk, FP, 2*FP, 0, s_ent, s_rp);      // S x1 (cheb folded into W')
    __syncthreads();
    gemm_run<4,4,128,FP>(xk, wgh, wgl, gb, H, us, 0, FX,
                         nullptr, nullptr, nullptr, nullptr, As_hi, As_lo, s_red);
    __syncthreads();
    sp_apply<FP>(xk, 0,  FP,   FX & ~3, s_ent, s_rp); // S rh (boundary cols recomputed, identical)
    __syncthreads();
    sp_apply<FP>(xk, FP, 2*FP, FX & ~3, s_ent, s_rp); // S (S rh)
    __syncthreads();
    gemm_run<8,2,64,FP>(xk, wch, wcl, cb, H, us, epi_cand, FX,
                        pW, pb, out_t, din, As_hi, As_lo, s_red);
    __syncthreads();
}

// ---------------- the whole network: one CTA per batch, no grid sync ----------------
__global__ void __launch_bounds__(NTH, 1)
dcrnn_batch(const float* __restrict__ inputs,
            const float* e0gb, const float* e0cb,
            const float* e1gb, const float* e1cb,
            const float* d0gb, const float* d0cb,
            const float* d1gb, const float* d1cb,
            const float* pW, const float* pb, float* __restrict__ out)
{
    __shared__ ull s_ent[MAXE];                       // 20.8 KB
    __shared__ int s_rp[NNODES+1];
    __shared__ __nv_bfloat16 As_hi[256*ASTR];         // 12 KB
    __shared__ __nv_bfloat16 As_lo[256*ASTR];         // 12 KB
    __shared__ float s_red[256*2];                    // 2 KB

    const int b = blockIdx.x, tid = threadIdx.x;
    float* xk  = g_xk  + (size_t)b*XKSTR;
    float* h0  = g_h0  + (size_t)b*NNODES*UNITS;
    float* h1  = g_h1  + (size_t)b*NNODES*UNITS;
    float* us  = g_u   + (size_t)b*NNODES*UNITS;
    float* din = g_din + (size_t)b*NNODES;

    // CSR -> smem (packed (val,col) 8B entries)
    int nnz = g_rowptr[NNODES]; if (nnz > MAXE) nnz = MAXE;
    for (int j = tid; j < nnz; j += NTH)
        s_ent[j] = ((ull)__float_as_uint(g_vals[j]) << 32) | (unsigned)g_cols[j];
    for (int r = tid; r <= NNODES; r += NTH)
        s_rp[r] = (g_rowptr[r] > MAXE) ? MAXE : g_rowptr[r];
    // zero state
    for (int i = tid; i < NNODES*UNITS; i += NTH){ h0[i] = 0.f; h1[i] = 0.f; }
    for (int i = tid; i < NNODES; i += NTH) din[i] = 0.f;
    __syncthreads();

    // ---- encoder ----
    for (int t = 0; t < TSTEPS; t++){
        const float* xin = inputs + ((size_t)t*BATCH + b)*NNODES*DIN;
        cell_run<2,66,68>(xk, xin, h0, us,
                          g_wph[0], g_wpl[0], e0gb, g_wph[4], g_wpl[4], e0cb,
                          1, nullptr, nullptr, nullptr, din,
                          s_ent, s_rp, As_hi, As_lo, s_red);
        cell_run<64,128,128>(xk, h0, h1, us,
                          g_wph[1], g_wpl[1], e1gb, g_wph[5], g_wpl[5], e1cb,
                          1, nullptr, nullptr, nullptr, din,
                          s_ent, s_rp, As_hi, As_lo, s_red);
    }
    // ---- decoder ----
    for (int t = 0; t < HORIZON; t++){
        cell_run<1,65,68>(xk, din, h0, us,
                          g_wph[2], g_wpl[2], d0gb, g_wph[6], g_wpl[6], d0cb,
                          1, nullptr, nullptr, nullptr, din,
                          s_ent, s_rp, As_hi, As_lo, s_red);
        cell_run<64,128,128>(xk, h0, h1, us,
                          g_wph[3], g_wpl[3], d1gb, g_wph[7], g_wpl[7], d1cb,
                          2, pW, pb,
                          out + ((size_t)t*BATCH + b)*NNODES, din,
                          s_ent, s_rp, As_hi, As_lo, s_red);
    }
}

extern "C" void kernel_launch(void* const* d_in, const int* in_sizes, int n_in,
                              void* d_out, int out_size)
{
    const float* inputs  = (const float*)d_in[0];
    const float* support = (const float*)d_in[1];
    const float* e0gW = (const float*)d_in[2];  const float* e0gb = (const float*)d_in[3];
    const float* e0cW = (const float*)d_in[4];  const float* e0cb = (const float*)d_in[5];
    const float* e1gW = (const float*)d_in[6];  const float* e1gb = (const float*)d_in[7];
    const float* e1cW = (const float*)d_in[8];  const float* e1cb = (const float*)d_in[9];
    const float* d0gW = (const float*)d_in[10]; const float* d0gb = (const float*)d_in[11];
    const float* d0cW = (const float*)d_in[12]; const float* d0cb = (const float*)d_in[13];
    const float* d1gW = (const float*)d_in[14]; const float* d1gb = (const float*)d_in[15];
    const float* d1cW = (const float*)d_in[16]; const float* d1cb = (const float*)d_in[17];
    const float* pW   = (const float*)d_in[18]; const float* pb   = (const float*)d_in[19];
    float* out = (float*)d_out;

    build_csr<<<1, 352>>>(support);
    // fold + frag-pack weights: gate mats 0..3, cand mats 4..7
    prep_w<<<48, 256>>>(e0gW, 66, 68, 128, 0);
    prep_w<<<48, 256>>>(e1gW, 128, 128, 128, 1);
    prep_w<<<48, 256>>>(d0gW, 65, 68, 128, 2);
    prep_w<<<48, 256>>>(d1gW, 128, 128, 128, 3);
    prep_w<<<48, 256>>>(e0cW, 66, 68, 64, 4);
    prep_w<<<48, 256>>>(e1cW, 128, 128, 64, 5);
    prep_w<<<48, 256>>>(d0cW, 65, 68, 64, 6);
    prep_w<<<48, 256>>>(d1cW, 128, 128, 64, 7);

    dcrnn_batch<<<BATCH, NTH>>>(inputs,
        e0gb, e0cb, e1gb, e1cb, d0gb, d0cb, d1gb, d1cb,
        pW, pb, out);
}

// round 12
// speedup vs baseline: 2.4578x; 1.1820x over previous
#include <cuda_runtime.h>
#include <cuda_bf16.h>
#include <math.h>

// ---------------- problem constants ----------------
#define NNODES 325
#define BATCH  64
#define TSTEPS 12
#define HORIZON 12
#define UNITS  64
#define DIN    2
#define XKSTR  (NNODES*384)
#define NTH    512
#define SPLIT  192               // rank0 rows [0,192) (=128+64 exact), rank1 [192,325)
#define MAXE   2600
#define WPMAX  32768
#define MAXNNZ 110000

typedef unsigned long long ull;
typedef __nv_bfloat16 bf16;

// ---------------- device scratch (A basis = [x,h]; B basis = [x,rh]) ----------------
__device__ __align__(16) float g_xkA[BATCH*XKSTR];
__device__ __align__(16) bf16  g_xhA[BATCH*XKSTR];
__device__ __align__(16) bf16  g_xlA[BATCH*XKSTR];
__device__ __align__(16) float g_xkB[BATCH*XKSTR];
__device__ __align__(16) bf16  g_xhB[BATCH*XKSTR];
__device__ __align__(16) bf16  g_xlB[BATCH*XKSTR];
__device__ float g_h0[BATCH*NNODES*UNITS];
__device__ float g_h1[BATCH*NNODES*UNITS];
__device__ float g_u [BATCH*NNODES*UNITS];
__device__ float g_din[BATCH*NNODES];
__device__ int   g_rowptr[NNODES+1];
__device__ int   g_cols[MAXNNZ];
__device__ float g_vals[MAXNNZ];
__device__ unsigned g_wph[8][WPMAX];
__device__ unsigned g_wpl[8][WPMAX];
__device__ unsigned g_pbar[BATCH];

__global__ void init_pbar(){ if (threadIdx.x < BATCH) g_pbar[threadIdx.x] = 0u; }

// ---------------- helpers ----------------
__device__ __forceinline__ void bfsplit(float a, bf16 &h, bf16 &l){
    h = __float2bfloat16(a);
    l = __float2bfloat16(a - __bfloat162float(h));
}
__device__ __forceinline__ void mma16816(float* d, const unsigned* a, const unsigned* b){
    asm volatile("mma.sync.aligned.m16n8k16.row.col.f32.bf16.bf16.f32 "
        "{%0,%1,%2,%3}, {%4,%5,%6,%7}, {%8,%9}, {%0,%1,%2,%3};"
        : "+f"(d[0]), "+f"(d[1]), "+f"(d[2]), "+f"(d[3])
        : "r"(a[0]), "r"(a[1]), "r"(a[2]), "r"(a[3]), "r"(b[0]), "r"(b[1]));
}
// pair barrier: monotonic counter, 2 CTAs/pair, 128 CTAs all resident
__device__ __forceinline__ void psync(unsigned* ctr, unsigned &ep){
    __threadfence();
    __syncthreads();
    if (threadIdx.x == 0){
        ep += 2;
        atomicAdd(ctr, 1u);
        while (*(volatile unsigned*)ctr < ep) { }
    }
    __syncthreads();
    __threadfence();
}

// ---------------- setup: compact CSR of S (proven R1) ----------------
__global__ void build_csr(const float* __restrict__ S){
    __shared__ int cnt[NNODES+1];
    int t = threadIdx.x;
    for (int r = t; r < NNODES; r += blockDim.x){
        int c = 0;
        for (int j = 0; j < NNODES; j++) c += (S[r*NNODES + j] != 0.0f);
        cnt[r] = c;
    }
    __syncthreads();
    if (t == 0){
        int acc = 0;
        for (int r = 0; r < NNODES; r++){ int c = cnt[r]; cnt[r] = acc; acc += c; }
        cnt[NNODES] = acc;
    }
    __syncthreads();
    for (int r = t; r <= NNODES; r += blockDim.x) g_rowptr[r] = cnt[r];
    for (int r = t; r < NNODES; r += blockDim.x){
        int p = cnt[r];
        for (int j = 0; j < NNODES; j++){
            float v = S[r*NNODES + j];
            if (v != 0.0f){ g_cols[p] = j; g_vals[p] = v; p++; }
        }
    }
}

// ---------------- setup: folded + frag-packed weights (proven R9) ----------------
__device__ __forceinline__ float wmod(const float* W, int F, int FP, int ONUM, int k, int n){
    int sec = k / FP, col = k - sec*FP;
    if (sec > 2 || col >= F) return 0.f;
    if (sec == 0) return W[col*ONUM + n] - W[(2*F + col)*ONUM + n];
    if (sec == 1) return W[(F + col)*ONUM + n];
    return 2.f*W[(2*F + col)*ONUM + n];
}
__global__ void prep_w(const float* __restrict__ W, int F, int FP, int ONUM, int mat){
    int F3P = 3*FP, NKT = (F3P + 15)/16, NB8 = ONUM/8;
    int total = NB8*NKT*64;
    for (int idx = blockIdx.x*blockDim.x + threadIdx.x; idx < total; idx += gridDim.x*blockDim.x){
        int reg = idx & 1, lane = (idx >> 1) & 31;
        int t2 = idx >> 6; int kt = t2 % NKT, nb8 = t2 / NKT;
        int gg = lane >> 2, qq = lane & 3;
        int n  = nb8*8 + gg;
        int k0 = kt*16 + qq*2 + reg*8;
        float w0 = wmod(W, F, FP, ONUM, k0,     n);
        float w1 = wmod(W, F, FP, ONUM, k0 + 1, n);
        bf16 h0,l0,h1,l1; bfsplit(w0,h0,l0); bfsplit(w1,h1,l1);
        g_wph[mat][idx] = (unsigned)__bfloat16_as_ushort(h0) | ((unsigned)__bfloat16_as_ushort(h1) << 16);
        g_wpl[mat][idx] = (unsigned)__bfloat16_as_ushort(l0) | ((unsigned)__bfloat16_as_ushort(l1) << 16);
    }
}

// ---------------- sparse apply: own rows, gathers all rows, float4 cols ----------------
template<int FP, int STRR, bool WF32>
__device__ void sp_apply(float* xk, bf16* xh, bf16* xl, int src, int dst,
                         const ull* s_ent, const int* s_rp, int rbeg, int rend)
{
    const int G = FP >> 2;
    const int tasks = (rend - rbeg)*G;
    for (int t = threadIdx.x; t < tasks; t += NTH){
        int m = rbeg + t/G, f = (t - (t/G)*G)*4;
        const float* sp = xk + src + f;
        float ax = 0.f, ay = 0.f, az = 0.f, aw = 0.f;
        int j = s_rp[m], j1 = s_rp[m+1];
        for (; j + 1 < j1; j += 2){
            ull e0 = s_ent[j], e1 = s_ent[j+1];
            float v0 = __uint_as_float((unsigned)(e0 >> 32));
            float v1 = __uint_as_float((unsigned)(e1 >> 32));
            float4 x0 = *(const float4*)(sp + (int)(unsigned)e0 * STRR);
            float4 x1 = *(const float4*)(sp + (int)(unsigned)e1 * STRR);
            ax += v0*x0.x + v1*x1.x;  ay += v0*x0.y + v1*x1.y;
            az += v0*x0.z + v1*x1.z;  aw += v0*x0.w + v1*x1.w;
        }
        if (j < j1){
            ull e0 = s_ent[j];
            float v0 = __uint_as_float((unsigned)(e0 >> 32));
            float4 x0 = *(const float4*)(sp + (int)(unsigned)e0 * STRR);
            ax += v0*x0.x; ay += v0*x0.y; az += v0*x0.z; aw += v0*x0.w;
        }
        int o = m*STRR + dst + f;
        if (WF32) *(float4*)(xk + o) = make_float4(ax, ay, az, aw);
        bf16 hx,lx,hy,ly,hz,lz,hw,lw;
        bfsplit(ax,hx,lx); bfsplit(ay,hy,ly); bfsplit(az,hz,lz); bfsplit(aw,hw,lw);
        uint2 uh, ul2;
        uh.x  = (unsigned)__bfloat16_as_ushort(hx) | ((unsigned)__bfloat16_as_ushort(hy) << 16);
        uh.y  = (unsigned)__bfloat16_as_ushort(hz) | ((unsigned)__bfloat16_as_ushort(hw) << 16);
        ul2.x = (unsigned)__bfloat16_as_ushort(lx) | ((unsigned)__bfloat16_as_ushort(ly) << 16);
        ul2.y = (unsigned)__bfloat16_as_ushort(lz) | ((unsigned)__bfloat16_as_ushort(lw) << 16);
        *(uint2*)(xh + o) = uh;
        *(uint2*)(xl + o) = ul2;
    }
}

// ---------------- barrier-free mma GEMM chunk (direct-LDG A frags; reads OWN rows only) ----------------
// epi 0 (gate): s=sigmoid; n<64 -> rh into B buffers x0[FX+n]; n>=64 -> g_u
// epi 1 (cand): c=tanh; H = u*H + (1-u)*c
// epi 2: epi1 + fused projection -> out_t, din
template<int MW, int NW, int ONUM, int FP, int STRR>
__device__ void gemm_chunk(int row0, int rowEnd,
    const bf16* __restrict__ xh, const bf16* __restrict__ xl,   // A-frag source
    float* xkB, bf16* xhB, bf16* xlB,                           // gate rh target (epi 0)
    const unsigned* __restrict__ wph, const unsigned* __restrict__ wpl,
    const float* __restrict__ bias, float* H, float* us, int epi, int FX,
    const float* __restrict__ pW, const float* __restrict__ pb,
    float* __restrict__ out_t, float* __restrict__ din, float* s_red)
{
    constexpr int NKT = (3*FP + 15)/16;
    constexpr int NA  = ONUM/(8*NW);
    constexpr int BM  = MW*32;
    const int tid = threadIdx.x, lane = tid & 31, wid = tid >> 5;
    const int mw = wid % MW, nw = wid / MW;
    const int g = lane >> 2, q = lane & 3;

    int aoff[4];
    #pragma unroll
    for (int i = 0; i < 4; i++){
        int r = row0 + mw*32 + i*8 + g;
        if (r > NNODES-1) r = NNODES-1;        // clamp stays in own-rank rows (SPLIT=192)
        aoff[i] = r*STRR + q*2;
    }

    float acc[2][NA][4];
    #pragma unroll
    for (int i = 0; i < 2; i++)
        #pragma unroll
        for (int j = 0; j < NA; j++)
            #pragma unroll
            for (int k = 0; k < 4; k++) acc[i][j][k] = 0.f;

    unsigned aH[2][2][4], aL[2][2][4], bB[2][NA][4];

    auto ldA = [&](int kt, int st){
        int kk = kt*16;
        #pragma unroll
        for (int ma = 0; ma < 2; ma++){
            aH[st][ma][0] = *(const unsigned*)(xh + aoff[2*ma]   + kk);
            aH[st][ma][1] = *(const unsigned*)(xh + aoff[2*ma+1] + kk);
            aH[st][ma][2] = *(const unsigned*)(xh + aoff[2*ma]   + kk + 8);
            aH[st][ma][3] = *(const unsigned*)(xh + aoff[2*ma+1] + kk + 8);
            aL[st][ma][0] = *(const unsigned*)(xl + aoff[2*ma]   + kk);
            aL[st][ma][1] = *(const unsigned*)(xl + aoff[2*ma+1] + kk);
            aL[st][ma][2] = *(const unsigned*)(xl + aoff[2*ma]   + kk + 8);
            aL[st][ma][3] = *(const unsigned*)(xl + aoff[2*ma+1] + kk + 8);
        }
    };
    auto ldB = [&](int kt, int st){
        #pragma unroll
        for (int na = 0; na < NA; na++){
            int base = (((nw*NA + na)*NKT + kt)*32 + lane)*2;
            uint2 bh = *(const uint2*)(wph + base);
            uint2 bl = *(const uint2*)(wpl + base);
            bB[st][na][0] = bh.x; bB[st][na][1] = bh.y;
            bB[st][na][2] = bl.x; bB[st][na][3] = bl.y;
        }
    };

    ldA(0, 0); ldB(0, 0);
    for (int kt = 0; kt < NKT; kt++){
        int cur = kt & 1, nxt = cur ^ 1;
        if (kt + 1 < NKT){ ldA(kt+1, nxt); ldB(kt+1, nxt); }
        #pragma unroll
        for (int na = 0; na < NA; na++){
            unsigned bh[2] = {bB[cur][na][0], bB[cur][na][1]};
            unsigned bl[2] = {bB[cur][na][2], bB[cur][na][3]};
            #pragma unroll
            for (int ma = 0; ma < 2; ma++){
                mma16816(acc[ma][na], aH[cur][ma], bh);
                mma16816(acc[ma][na], aH[cur][ma], bl);
                mma16816(acc[ma][na], aL[cur][ma], bh);
            }
        }
    }

    float pvp[2][2] = {{0.f,0.f},{0.f,0.f}};
    #pragma unroll
    for (int ma = 0; ma < 2; ma++){
        #pragma unroll
        for (int na = 0; na < NA; na++){
            int n0 = nw*(8*NA) + na*8 + q*2;
            #pragma unroll
            for (int half = 0; half < 2; half++){
                int r = row0 + mw*32 + ma*16 + g + half*8;
                if (r >= rowEnd) continue;
                float v0 = acc[ma][na][half*2 + 0] + bias[n0];
                float v1 = acc[ma][na][half*2 + 1] + bias[n0 + 1];
                if (epi == 0){
                    float s0 = 1.f/(1.f + expf(-v0));
                    float s1 = 1.f/(1.f + expf(-v1));
                    if (n0 < UNITS){
                        float r0 = s0 * H[r*UNITS + n0];
                        float r1 = s1 * H[r*UNITS + n0 + 1];
                        int o = r*STRR + FX + n0;
                        xkB[o] = r0; xkB[o+1] = r1;            // cand basis (B), not read this phase
                        bf16 h, l;
                        bfsplit(r0, h, l); xhB[o] = h;   xlB[o] = l;
                        bfsplit(r1, h, l); xhB[o+1] = h; xlB[o+1] = l;
                    } else {
                        us[r*UNITS + (n0 - UNITS)]     = s0;
                        us[r*UNITS + (n0 - UNITS) + 1] = s1;
                    }
                } else {
                    float c0 = tanhf(v0), c1 = tanhf(v1);
                    float u0 = us[r*UNITS + n0],     u1 = us[r*UNITS + n0 + 1];
                    float h0v = H[r*UNITS + n0],     h1v = H[r*UNITS + n0 + 1];
                    float hn0 = u0*h0v + (1.f - u0)*c0;
                    float hn1 = u1*h1v + (1.f - u1)*c1;
                    H[r*UNITS + n0]     = hn0;
                    H[r*UNITS + n0 + 1] = hn1;
                    if (epi == 2) pvp[ma][half] += hn0*pW[n0] + hn1*pW[n0 + 1];
                }
            }
        }
    }
    if (epi == 2){
        #pragma unroll
        for (int ma = 0; ma < 2; ma++)
            #pragma unroll
            for (int half = 0; half < 2; half++){
                float v = pvp[ma][half];
                v += __shfl_down_sync(0xffffffffu, v, 2);
                v += __shfl_down_sync(0xffffffffu, v, 1);
                if (q == 0) s_red[(mw*32 + ma*16 + g + half*8)*NW + nw] = v;
            }
        __syncthreads();
        if (tid < BM){
            int r = row0 + tid;
            if (r < rowEnd){
                float v = pb[0];
                #pragma unroll
                for (int w2 = 0; w2 < NW; w2++) v += s_red[tid*NW + w2];
                din[r]  = v;
                out_t[r] = v;
            }
        }
        __syncthreads();
    }
}

// ---------------- one GRU cell (5 pair-syncs; cell-end psync kills stride-crossing races) ----------------
template<int FX, int F, int FP, int STRR>
__device__ void cell_run(int b, int rbeg, int rend,
                         const float* __restrict__ xptr, float* H,
                         int matg, int matc,
                         const float* gb, const float* cb, int epi_cand,
                         const float* pW, const float* pb, float* out_t,
                         unsigned* ctr, unsigned &ep,
                         const ull* s_ent, const int* s_rp, float* s_red)
{
    float* xkA = g_xkA + b*XKSTR;  bf16* xhA = g_xhA + b*XKSTR;  bf16* xlA = g_xlA + b*XKSTR;
    float* xkB = g_xkB + b*XKSTR;  bf16* xhB = g_xhB + b*XKSTR;  bf16* xlB = g_xlB + b*XKSTR;
    float* us  = g_u   + b*NNODES*UNITS;
    float* din = g_din + b*NNODES;

    __syncthreads();   // prev-cell H/din (in-CTA); cross-CTA handled by cell-end psync
    // concat: A.x0 = [x, h] + pads ; B.x0 x-cols + pads (rh cols filled by gate epi)
    for (int idx = threadIdx.x; idx < (rend - rbeg)*FP; idx += NTH){
        int m = rbeg + idx/FP, f = idx - (idx/FP)*FP;
        int o = m*STRR + f;
        float v;
        bf16 h, l;
        if (f >= F){
            xkA[o] = 0.f; xhA[o] = __float2bfloat16(0.f); xlA[o] = __float2bfloat16(0.f);
            xkB[o] = 0.f; xhB[o] = __float2bfloat16(0.f); xlB[o] = __float2bfloat16(0.f);
            continue;
        }
        if (f < FX){
            v = (FX == 2) ? xptr[m*DIN + f] : ((FX == 1) ? xptr[m] : xptr[m*UNITS + f]);
            bfsplit(v, h, l);
            xkA[o] = v; xhA[o] = h; xlA[o] = l;
            xkB[o] = v; xhB[o] = h; xlB[o] = l;      // x-cols shared by both bases
        } else {
            v = H[m*UNITS + (f - FX)];
            bfsplit(v, h, l);
            xkA[o] = v; xhA[o] = h; xlA[o] = l;
        }
    }
    psync(ctr, ep);                                                    // (a) x0 all rows ready
    sp_apply<FP,STRR,true >(xkA, xhA, xlA, 0,  FP,   s_ent, s_rp, rbeg, rend);   // A: S x0
    psync(ctr, ep);                                                    // (b) x1 all rows ready
    sp_apply<FP,STRR,false>(xkA, xhA, xlA, FP, 2*FP, s_ent, s_rp, rbeg, rend);   // A: S x1
    __syncthreads();                                                   // own rows only below
    gemm_chunk<4,4,128,FP,STRR>(rbeg,       rend, xhA, xlA, xkB, xhB, xlB,
        g_wph[matg], g_wpl[matg], gb, H, us, 0, FX, nullptr, nullptr, nullptr, din, s_red);
    gemm_chunk<2,8,128,FP,STRR>(rbeg + 128, rend, xhA, xlA, xkB, xhB, xlB,
        g_wph[matg], g_wpl[matg], gb, H, us, 0, FX, nullptr, nullptr, nullptr, din, s_red);
    psync(ctr, ep);                                                    // (c) B.x0 (rh) all rows
    sp_apply<FP,STRR,true >(xkB, xhB, xlB, 0,  FP,   s_ent, s_rp, rbeg, rend);   // B: S [x,rh]
    psync(ctr, ep);                                                    // (d) B.x1 all rows
    sp_apply<FP,STRR,false>(xkB, xhB, xlB, FP, 2*FP, s_ent, s_rp, rbeg, rend);   // B: S (S [x,rh])
    __syncthreads();                                                   // own rows only below
    gemm_chunk<4,4,64,FP,STRR>(rbeg,       rend, xhB, xlB, xkB, xhB, xlB,
        g_wph[matc], g_wpl[matc], cb, H, us, epi_cand, FX, pW, pb, out_t, din, s_red);
    gemm_chunk<2,8,64,FP,STRR>(rbeg + 128, rend, xhB, xlB, xkB, xhB, xlB,
        g_wph[matc], g_wpl[matc], cb, H, us, epi_cand, FX, pW, pb, out_t, din, s_red);
    psync(ctr, ep);          // (e) CELL END: peer must finish cand GEMM before next-cell
                             //     concat re-writes buffers in a DIFFERENT stride layout
}

// ---------------- the whole network: 2 CTAs per batch (node split at 192) ----------------
__global__ void __launch_bounds__(NTH, 1)
dcrnn_pair(const float* __restrict__ inputs,
           const float* e0gb, const float* e0cb,
           const float* e1gb, const float* e1cb,
           const float* d0gb, const float* d0cb,
           const float* d1gb, const float* d1cb,
           const float* pW, const float* pb, float* __restrict__ out)
{
    __shared__ ull s_ent[MAXE];
    __shared__ int s_rp[NNODES+1];
    __shared__ float s_red[128*8];

    const int b = blockIdx.x >> 1, rank = blockIdx.x & 1;
    const int rbeg = rank ? SPLIT : 0;
    const int rend = rank ? NNODES : SPLIT;
    const int tid = threadIdx.x;
    unsigned* ctr = &g_pbar[b];
    unsigned ep = 0;

    // CSR -> smem
    int nnz = g_rowptr[NNODES]; if (nnz > MAXE) nnz = MAXE;
    for (int j = tid; j < nnz; j += NTH)
        s_ent[j] = ((ull)__float_as_uint(g_vals[j]) << 32) | (unsigned)g_cols[j];
    for (int r = tid; r <= NNODES; r += NTH)
        s_rp[r] = (g_rowptr[r] > MAXE) ? MAXE : g_rowptr[r];
    // zero own state
    float* h0  = g_h0 + b*NNODES*UNITS;
    float* h1  = g_h1 + b*NNODES*UNITS;
    float* din = g_din + b*NNODES;
    for (int i = tid; i < (rend - rbeg)*UNITS; i += NTH)
        { h0[rbeg*UNITS + i] = 0.f; h1[rbeg*UNITS + i] = 0.f; }
    for (int i = tid; i < rend - rbeg; i += NTH) din[rbeg + i] = 0.f;

    // ---- encoder ----
    for (int t = 0; t < TSTEPS; t++){
        const float* xin = inputs + ((size_t)t*BATCH + b)*NNODES*DIN;
        cell_run<2,66,68,208>(b, rbeg, rend, xin, h0, 0, 4, e0gb, e0cb, 1,
                              nullptr, nullptr, nullptr, ctr, ep, s_ent, s_rp, s_red);
        cell_run<64,128,128,384>(b, rbeg, rend, h0, h1, 1, 5, e1gb, e1cb, 1,
                              nullptr, nullptr, nullptr, ctr, ep, s_ent, s_rp, s_red);
    }
    // ---- decoder ----
    for (int t = 0; t < HORIZON; t++){
        cell_run<1,65,68,208>(b, rbeg, rend, din, h0, 2, 6, d0gb, d0cb, 1,
                              nullptr, nullptr, nullptr, ctr, ep, s_ent, s_rp, s_red);
        cell_run<64,128,128,384>(b, rbeg, rend, h0, h1, 3, 7, d1gb, d1cb, 2,
                              pW, pb, out + ((size_t)t*BATCH + b)*NNODES,
                              ctr, ep, s_ent, s_rp, s_red);
    }
}

extern "C" void kernel_launch(void* const* d_in, const int* in_sizes, int n_in,
                              void* d_out, int out_size)
{
    const float* inputs  = (const float*)d_in[0];
    const float* support = (const float*)d_in[1];
    const float* e0gW = (const float*)d_in[2];  const float* e0gb = (const float*)d_in[3];
    const float* e0cW = (const float*)d_in[4];  const float* e0cb = (const float*)d_in[5];
    const float* e1gW = (const float*)d_in[6];  const float* e1gb = (const float*)d_in[7];
    const float* e1cW = (const float*)d_in[8];  const float* e1cb = (const float*)d_in[9];
    const float* d0gW = (const float*)d_in[10]; const float* d0gb = (const float*)d_in[11];
    const float* d0cW = (const float*)d_in[12]; const float* d0cb = (const float*)d_in[13];
    const float* d1gW = (const float*)d_in[14]; const float* d1gb = (const float*)d_in[15];
    const float* d1cW = (const float*)d_in[16]; const float* d1cb = (const float*)d_in[17];
    const float* pW   = (const float*)d_in[18]; const float* pb   = (const float*)d_in[19];
    float* out = (float*)d_out;

    init_pbar<<<1, BATCH>>>();
    build_csr<<<1, 352>>>(support);
    // fold + frag-pack weights: gate mats 0..3, cand mats 4..7
    prep_w<<<48, 256>>>(e0gW, 66, 68, 128, 0);
    prep_w<<<48, 256>>>(e1gW, 128, 128, 128, 1);
    prep_w<<<48, 256>>>(d0gW, 65, 68, 128, 2);
    prep_w<<<48, 256>>>(d1gW, 128, 128, 128, 3);
    prep_w<<<48, 256>>>(e0cW, 66, 68, 64, 4);
    prep_w<<<48, 256>>>(e1cW, 128, 128, 64, 5);
    prep_w<<<48, 256>>>(d0cW, 65, 68, 64, 6);
    prep_w<<<48, 256>>>(d1cW, 128, 128, 64, 7);

    dcrnn_pair<<<2*BATCH, NTH>>>(inputs,
        e0gb, e0cb, e1gb, e1cb, d0gb, d0cb, d1gb, d1cb,
        pW, pb, out);
}